// round 10
// baseline (speedup 1.0000x reference)
#include <cuda_runtime.h>
#include <cuda_fp16.h>
#include <cstdint>

// out[1024,4096] = tanh(x[1024,8192] @ scatter(W[8192,4096]) + bias)
// sm_100 base target (no tcgen05): cp.async + ldmatrix + mma.m16n8k16 (f16 acc).
// Model fit over R6-R9: fp32-accum HMMA = rt16/SMSP (saturated); fp16-accum =
// rt8. This round: accumulate in f16 across each K=64 iter (4 chained MMAs),
// promote to fp32 per iter. Predicted +1.5e-4 rel err, GEMM ~2x faster.

#define D_DIM 8192
#define U_DIM 4096
#define B_ROWS 1024

#define MT 128
#define NT 256
#define KC 64
#define PITCH 72                           // halves per smem row (144 B, 16B-aligned)
#define A_ST (MT * PITCH)                  // 9216 halves
#define B_ST (NT * PITCH)                  // 18432 halves
#define STG_H (A_ST + B_ST)                // 27648 halves
#define N_STAGES 4
#define SMEM_DYN (N_STAGES * STG_H * 2)    // 221184 B
#define N_ITER (D_DIM / KC)                // 128

__device__ __half g_W[(size_t)U_DIM * D_DIM];  // Wt[u][d], 64 MB
__device__ __half g_X[(size_t)B_ROWS * D_DIM]; // fp16 x, 16 MB

// ---------------------------------------------------------------- helpers
__device__ __forceinline__ uint32_t smem_u32(const void* p) {
    uint32_t a;
    asm("{ .reg .u64 t; cvta.to.shared.u64 t, %1; cvt.u32.u64 %0, t; }"
        : "=r"(a) : "l"(p));
    return a;
}

// f16-accumulate HMMA (full-rate): C/D packed as 2x b32 (4 halves)
__device__ __forceinline__ void mma_f16acc(uint32_t* c, const uint32_t* a, const uint32_t* b) {
    asm volatile(
        "mma.sync.aligned.m16n8k16.row.col.f16.f16.f16.f16 "
        "{%0,%1}, {%2,%3,%4,%5}, {%6,%7}, {%0,%1};"
        : "+r"(c[0]), "+r"(c[1])
        : "r"(a[0]), "r"(a[1]), "r"(a[2]), "r"(a[3]), "r"(b[0]), "r"(b[1]));
}

#define LDMATRIX_X4(r0, r1, r2, r3, addr) \
    asm volatile("ldmatrix.sync.aligned.m8n8.x4.shared.b16 {%0,%1,%2,%3}, [%4];" \
                 : "=r"(r0), "=r"(r1), "=r"(r2), "=r"(r3) : "r"(addr))

#define CP_ASYNC16(sm, gp) \
    asm volatile("cp.async.cg.shared.global [%0], [%1], 16;" \
                 :: "r"(sm), "l"(gp) : "memory")
#define CP_COMMIT()  asm volatile("cp.async.commit_group;" ::: "memory")
#define CP_WAIT2()   asm volatile("cp.async.wait_group 2;" ::: "memory")

// ---------------------------------------------------------------- pre-passes
__global__ void conv_x_kernel(const float4* __restrict__ in, uint2* __restrict__ outp, int n4) {
    int i = blockIdx.x * blockDim.x + threadIdx.x;
    if (i < n4) {
        float4 v = in[i];
        __half2 lo = __floats2half2_rn(v.x, v.y);
        __half2 hi = __floats2half2_rn(v.z, v.w);
        outp[i] = make_uint2(*(uint32_t*)&lo, *(uint32_t*)&hi);
    }
}

__global__ void scatter_kernel(const int2* __restrict__ ind, const float* __restrict__ val,
                               __half* __restrict__ W, int nnz) {
    int i = blockIdx.x * blockDim.x + threadIdx.x;
    if (i < nnz) {
        int2 du = ind[i];  // .x = d (row of dense W), .y = u (col)
        atomicAdd(W + ((size_t)du.y * D_DIM + du.x), __float2half(val[i]));
    }
}

// ---------------------------------------------------------------- GEMM
__global__ void __launch_bounds__(256, 1)
sparse_gemm_kernel(const __half* __restrict__ gA,   // g_X [1024][8192]
                   const __half* __restrict__ gB,   // g_W [4096][8192]
                   const float* __restrict__ bias,
                   float* __restrict__ out) {
    extern __shared__ __half smem[];
    uint32_t sbase = smem_u32(smem);

    const int tid  = threadIdx.x;
    const int lane = tid & 31;
    const int wid  = tid >> 5;
    const int wm   = wid >> 2;        // 0..1 -> rows wm*64
    const int wn   = wid & 3;         // 0..3 -> cols wn*64
    const int mt = blockIdx.x & 7;    // consecutive bx share an N-tile (W L2 reuse)
    const int nt = blockIdx.x >> 3;
    const int m0 = mt * MT, n0 = nt * NT;

    // ldmatrix per-thread selectors (byte offsets within a stage)
    const int am = (((lane >> 3) & 1) << 3) + (lane & 7);
    const int ak = (lane >> 4) << 3;
    const int bn = ((lane >> 4) << 3) + (lane & 7);
    const int bk = (((lane >> 3) & 1)) << 3;

    uint32_t aoff[4], boff[4];
#pragma unroll
    for (int f = 0; f < 4; f++)
        aoff[f] = (uint32_t)(((wm * 64 + f * 16 + am) * PITCH + ak) * 2);
#pragma unroll
    for (int p = 0; p < 4; p++)
        boff[p] = (uint32_t)(A_ST * 2 + ((wn * 64 + p * 16 + bn) * PITCH + bk) * 2);

    float acc[4][8][4];
#pragma unroll
    for (int f = 0; f < 4; f++)
#pragma unroll
        for (int bf = 0; bf < 8; bf++)
#pragma unroll
            for (int k = 0; k < 4; k++) acc[f][bf][k] = 0.f;

    // ---- stage loader: 128x64 A + 256x64 B halves, 16B chunks, 12/thread ----
    auto stage_load = [&](int s, int kt) {
        uint32_t sA = sbase + (uint32_t)(s * STG_H) * 2u;
        uint32_t sB = sA + (uint32_t)A_ST * 2u;
        const __half* ga = gA + (size_t)m0 * D_DIM + kt * KC;
        const __half* gb = gB + (size_t)n0 * D_DIM + kt * KC;
#pragma unroll
        for (int i = 0; i < 4; i++) {                 // A: 1024 chunks
            int ch = tid + i * 256, row = ch >> 3, cc = ch & 7;
            CP_ASYNC16(sA + (uint32_t)(row * PITCH + cc * 8) * 2u,
                       ga + (size_t)row * D_DIM + cc * 8);
        }
#pragma unroll
        for (int i = 0; i < 8; i++) {                 // B: 2048 chunks
            int ch = tid + i * 256, row = ch >> 3, cc = ch & 7;
            CP_ASYNC16(sB + (uint32_t)(row * PITCH + cc * 8) * 2u,
                       gb + (size_t)row * D_DIM + cc * 8);
        }
    };

#pragma unroll
    for (int s = 0; s < 3; s++) { stage_load(s, s); CP_COMMIT(); }

    for (int it = 0; it < N_ITER; it++) {
        const int s = it & (N_STAGES - 1);
        CP_WAIT2();
        __syncthreads();
        if (it + 3 < N_ITER) stage_load((it + 3) & (N_STAGES - 1), it + 3);
        CP_COMMIT();

        const uint32_t stg = sbase + (uint32_t)(s * STG_H) * 2u;

        // f16 accumulators for this K=64 chunk (zeroed each iter)
        uint32_t hacc[4][8][2];
#pragma unroll
        for (int f = 0; f < 4; f++)
#pragma unroll
            for (int bf = 0; bf < 8; bf++) {
                hacc[f][bf][0] = 0u; hacc[f][bf][1] = 0u;
            }

#pragma unroll
        for (int kk = 0; kk < 4; kk++) {
            const uint32_t kb = (uint32_t)(kk * 32);      // 32 B per k-step
            uint32_t a[4][4], b[4][4];
#pragma unroll
            for (int f = 0; f < 4; f++)
                LDMATRIX_X4(a[f][0], a[f][1], a[f][2], a[f][3], stg + aoff[f] + kb);
#pragma unroll
            for (int p = 0; p < 4; p++)
                LDMATRIX_X4(b[p][0], b[p][1], b[p][2], b[p][3], stg + boff[p] + kb);
#pragma unroll
            for (int bf = 0; bf < 8; bf++)
#pragma unroll
                for (int f = 0; f < 4; f++)
                    mma_f16acc(hacc[f][bf], a[f], &b[bf >> 1][(bf & 1) << 1]);
        }

        // promote chunk sums to fp32
#pragma unroll
        for (int f = 0; f < 4; f++)
#pragma unroll
            for (int bf = 0; bf < 8; bf++) {
                float2 p0 = __half22float2(*(__half2*)&hacc[f][bf][0]);
                float2 p1 = __half22float2(*(__half2*)&hacc[f][bf][1]);
                acc[f][bf][0] += p0.x; acc[f][bf][1] += p0.y;
                acc[f][bf][2] += p1.x; acc[f][bf][3] += p1.y;
            }
    }

    // ---- epilogue: bias + tanh, float2 stores ----
#pragma unroll
    for (int f = 0; f < 4; f++) {
        const int r0 = m0 + wm * 64 + f * 16 + (lane >> 2);
#pragma unroll
        for (int bf = 0; bf < 8; bf++) {
            const int cb = n0 + wn * 64 + bf * 8 + 2 * (lane & 3);
            const float b0 = __ldg(bias + cb), b1 = __ldg(bias + cb + 1);
            float2 v0 = {tanhf(acc[f][bf][0] + b0), tanhf(acc[f][bf][1] + b1)};
            float2 v1 = {tanhf(acc[f][bf][2] + b0), tanhf(acc[f][bf][3] + b1)};
            *(float2*)(out + (size_t)r0 * U_DIM + cb) = v0;
            *(float2*)(out + (size_t)(r0 + 8) * U_DIM + cb) = v1;
        }
    }
}

// ---------------------------------------------------------------- host side
extern "C" void kernel_launch(void* const* d_in, const int* in_sizes, int n_in,
                              void* d_out, int out_size) {
    const float* x    = (const float*)d_in[0];
    const float* kv   = (const float*)d_in[1];
    const float* bias = (const float*)d_in[2];
    const int*   ind  = (const int*)d_in[3];
    float* out = (float*)d_out;
    int nnz = in_sizes[1];

    void* wptr = nullptr;
    void* xptr = nullptr;
    cudaGetSymbolAddress(&wptr, g_W);
    cudaGetSymbolAddress(&xptr, g_X);

    cudaFuncSetAttribute(sparse_gemm_kernel,
                         cudaFuncAttributeMaxDynamicSharedMemorySize, SMEM_DYN);

    cudaMemsetAsync(wptr, 0, (size_t)U_DIM * D_DIM * sizeof(__half));

    int n4 = B_ROWS * D_DIM / 4;
    conv_x_kernel<<<(n4 + 255) / 256, 256>>>((const float4*)x, (uint2*)xptr, n4);

    scatter_kernel<<<(nnz + 255) / 256, 256>>>((const int2*)ind, kv, (__half*)wptr, nnz);

    sparse_gemm_kernel<<<(B_ROWS / MT) * (U_DIM / NT), 256, SMEM_DYN>>>(
        (const __half*)xptr, (const __half*)wptr, bias, out);
}